// round 15
// baseline (speedup 1.0000x reference)
#include <cuda_runtime.h>
#include <stdint.h>
#include <math.h>

#define NTOT    (1<<22)
#define NBANDS  8
#define TPB     256

#define SC_CHUNK 2048
#define SC_NBLK  (NTOT/SC_CHUNK)   /* 2048 */
#define SC_L     (SC_CHUNK/TPB)    /* 8    */

#define R_CAP    540672             /* NTOT/8 + 16384 */

#define NT2      2560               /* value tiles */
#define CAP      2560               /* smem window slots */
#define WPT2     (CAP/TPB)          /* 10 */
#define NWARP    (TPB/32)           /* 8 */

#define VMIN     (-8.0)
#define VMAX     (10008.0)
#define WARMW    (1.25)

typedef unsigned long long ull;

// ---------------- static device scratch ----------------
__device__ ull    g_key[8*R_CAP];
__device__ int    g_bcnt[NBANDS*SC_NBLK];
__device__ int    g_boff[NBANDS*SC_NBLK];
__device__ int    g_cnt[NBANDS];
__device__ double g_bsum[NT2];
__device__ float  g_amps[NBANDS], g_lags[NBANDS], g_ka, g_kc;

__device__ __forceinline__ unsigned fkey(float f){
    unsigned u = __float_as_uint(f);
    return (u & 0x80000000u) ? ~u : (u | 0x80000000u);
}
__device__ __forceinline__ float unfkey(unsigned k){
    unsigned u = (k & 0x80000000u) ? (k & 0x7fffffffu) : ~k;
    return __uint_as_float(u);
}

__device__ __forceinline__ void mmulD(double r[4], const double n[4], const double o[4]){
    double t0 = n[0]*o[0] + n[1]*o[2];
    double t1 = n[0]*o[1] + n[1]*o[3];
    double t2 = n[2]*o[0] + n[3]*o[2];
    double t3 = n[2]*o[1] + n[3]*o[3];
    double mx = fmax(fmax(fabs(t0),fabs(t1)), fmax(fabs(t2),fabs(t3)));
    double s  = (mx > 0.0) ? 1.0/mx : 1.0;
    r[0]=t0*s; r[1]=t1*s; r[2]=t2*s; r[3]=t3*s;
}

// ---------------- params ----------------
__global__ void k_init(const float* __restrict__ lad, const float* __restrict__ lg,
                       const float* __restrict__ lkp){
    if (threadIdx.x == 0){
        g_amps[0] = 1.f; g_lags[0] = 0.f;
        for (int b = 1; b < NBANDS; b++){
            g_amps[b] = expf(lad[b-1]);
            g_lags[b] = lg[b-1];
        }
        g_ka = expf(lkp[0]);
        g_kc = expf(lkp[1]);
    }
}

// ---------------- stage 1: histogram (band-major) ----------------
__global__ void k_count(const int* __restrict__ band){
    __shared__ int sc[NBANDS];
    int tid = threadIdx.x;
    if (tid < NBANDS) sc[tid] = 0;
    __syncthreads();
    int cnt[NBANDS];
    #pragma unroll
    for (int b = 0; b < NBANDS; b++) cnt[b] = 0;
    int base = blockIdx.x * SC_CHUNK;
    for (int k = tid; k < SC_CHUNK; k += TPB) cnt[band[base+k]]++;
    #pragma unroll
    for (int b = 0; b < NBANDS; b++) if (cnt[b]) atomicAdd(&sc[b], cnt[b]);
    __syncthreads();
    if (tid < NBANDS) g_bcnt[tid*SC_NBLK + blockIdx.x] = sc[tid];
}

// ---------------- stage 1b: 8 independent per-band scans ----------------
__global__ void k_offsets8(){
    __shared__ int ssum[TPB];
    int b = blockIdx.x;
    int tid = threadIdx.x;
    int v[SC_NBLK/TPB];
    int run = 0;
    #pragma unroll
    for (int q = 0; q < SC_NBLK/TPB; q++){
        v[q] = run;
        run += g_bcnt[b*SC_NBLK + tid*(SC_NBLK/TPB) + q];
    }
    ssum[tid] = run;
    __syncthreads();
    for (int off = 1; off < TPB; off <<= 1){
        int pv = (tid >= off) ? ssum[tid-off] : 0;
        __syncthreads();
        ssum[tid] += pv;
        __syncthreads();
    }
    int excl = tid ? ssum[tid-1] : 0;
    #pragma unroll
    for (int q = 0; q < SC_NBLK/TPB; q++)
        g_boff[b*SC_NBLK + tid*(SC_NBLK/TPB) + q] = excl + v[q];
    if (tid == TPB-1) g_cnt[b] = excl + run;
}

// ---------------- stage 2: stable partition into band regions ----------------
__global__ void k_scatter(const float* __restrict__ t, const int* __restrict__ band){
    __shared__ float s_t[SC_CHUNK];
    __shared__ int   s_b[SC_CHUNK];
    __shared__ int   s_scan[NBANDS*TPB];
    __shared__ float s_lag[NBANDS];
    int tid = threadIdx.x;
    int base = blockIdx.x * SC_CHUNK;
    if (tid < NBANDS) s_lag[tid] = g_lags[tid];
    for (int k = tid; k < SC_CHUNK; k += TPB){
        s_t[k] = t[base+k]; s_b[k] = band[base+k];
    }
    __syncthreads();
    int cnt[NBANDS];
    #pragma unroll
    for (int b = 0; b < NBANDS; b++) cnt[b] = 0;
    #pragma unroll
    for (int j = 0; j < SC_L; j++) cnt[s_b[tid*SC_L + j]]++;
    #pragma unroll
    for (int b = 0; b < NBANDS; b++) s_scan[b*TPB + tid] = cnt[b];
    __syncthreads();
    for (int off = 1; off < TPB; off <<= 1){
        int v[NBANDS];
        #pragma unroll
        for (int b = 0; b < NBANDS; b++) v[b] = (tid >= off) ? s_scan[b*TPB + tid - off] : 0;
        __syncthreads();
        #pragma unroll
        for (int b = 0; b < NBANDS; b++) s_scan[b*TPB + tid] += v[b];
        __syncthreads();
    }
    int pos[NBANDS];
    #pragma unroll
    for (int b = 0; b < NBANDS; b++)
        pos[b] = b*R_CAP + g_boff[b*SC_NBLK + blockIdx.x] + (tid ? s_scan[b*TPB + tid - 1] : 0);
    #pragma unroll
    for (int j = 0; j < SC_L; j++){
        int li = tid*SC_L + j;
        int b = s_b[li];
        float nt = s_t[li] - s_lag[b];
        ull key = ((ull)fkey(nt) << 32) | ((ull)(unsigned)(base + li) << 3) | (unsigned)b;
        g_key[pos[b]++] = key;
    }
}

// ---------------- smem pairwise merge (strict total order: keys unique) ----------------
__device__ __forceinline__ void smem_merge(const ull* S, ull* D,
                                           int aOff, int aLen, int bOff, int bLen,
                                           int dOff, int lt, int nth){
    int total = aLen + bLen;
    if (total <= 0) return;
    int per = (total + nth - 1) / nth;
    int k0 = lt * per;
    if (k0 >= total) return;
    int k1 = k0 + per; if (k1 > total) k1 = total;
    int lo = k0 - bLen; if (lo < 0) lo = 0;
    int hi = k0 < aLen ? k0 : aLen;
    while (lo < hi){
        int mid = (lo + hi) >> 1;
        if (S[aOff + mid] < S[bOff + k0 - mid - 1]) lo = mid + 1; else hi = mid;
    }
    int i = lo, j = k0 - lo;
    for (int k = k0; k < k1; k++){
        bool ta = (j >= bLen) || (i < aLen && S[aOff + i] < S[bOff + j]);
        D[dOff + k] = ta ? S[aOff + i++] : S[bOff + j++];
    }
}

// ---------------- fused: value-window 8-way merge + warmup scans + quadratic likelihood ----------------
__global__ void __launch_bounds__(TPB)
k_fused8(const float* __restrict__ y, const float* __restrict__ dg){
    __shared__ __align__(16) char raw[CAP*16];
    ull*   bufA = (ull*)raw;
    ull*   bufB = (ull*)(raw + CAP*8);
    float* s_nt = (float*)raw;
    float* s_am = (float*)(raw + CAP*4);
    float* s_y  = (float*)(raw + CAP*8);
    float* s_dd = (float*)(raw + CAP*12);
    __shared__ int s_res[24];
    __shared__ int s_off[9], s_gs[8];
    __shared__ int s_nw, s_nv;
    __shared__ double sWin[NWARP][4];
    __shared__ double sAf[NWARP][2];
    __shared__ double sred[TPB];
    __shared__ float  sam[NBANDS];
    const unsigned FULL = 0xFFFFFFFFu;

    int tid = threadIdx.x;
    int lane = tid & 31;
    int wid  = tid >> 5;
    int blk  = blockIdx.x;

    double TW = (VMAX - VMIN) / (double)NT2;
    float vlo = (float)(VMIN + blk*TW);
    float vhi = (float)(VMIN + (blk+1)*TW);
    float wlo = (float)(VMIN + blk*TW - WARMW);

    if (tid < NBANDS) sam[tid] = g_amps[tid];
    if (tid < 24){
        int bb = tid / 3, w = tid % 3;
        float v = (w == 0) ? wlo : (w == 1 ? vlo : vhi);
        ull K = ((ull)fkey(v)) << 32;
        const ull* L = g_key + bb*R_CAP;
        int lo = 0, hi = g_cnt[bb];
        while (lo < hi){
            int mid = (lo + hi) >> 1;
            if (__ldg(&L[mid]) < K) lo = mid + 1; else hi = mid;
        }
        s_res[tid] = lo;
    }
    __syncthreads();
    if (tid == 0){
        int st[8], ln[8], wb[8];
        int tot = 0;
        #pragma unroll
        for (int q = 0; q < 8; q++){
            st[q] = s_res[q*3+0];
            wb[q] = s_res[q*3+1] - st[q];
            ln[q] = s_res[q*3+2] - st[q];
            tot += ln[q];
        }
        if (tot > CAP){   // defensive: trim warmup from left
            int drop = tot - CAP;
            for (int q = 0; q < 8 && drop > 0; q++){
                int d = wb[q] < drop ? wb[q] : drop;
                st[q] += d; ln[q] -= d; wb[q] -= d; drop -= d;
            }
            tot = 0;
            for (int q = 0; q < 8; q++) tot += ln[q];
        }
        int o = 0, nw = 0;
        #pragma unroll
        for (int q = 0; q < 8; q++){
            s_off[q] = o; s_gs[q] = st[q];
            o += ln[q]; nw += wb[q];
        }
        s_off[8] = o; s_nv = o; s_nw = nw;
    }
    __syncthreads();

    // load band segments (coalesced per band)
    #pragma unroll
    for (int q = 0; q < 8; q++){
        const ull* L = g_key + q*R_CAP + s_gs[q];
        int o  = s_off[q];
        int ln = s_off[q+1] - o;
        for (int k = tid; k < ln; k += TPB) bufA[o+k] = __ldg(&L[k]);
    }
    __syncthreads();

    // 3 rounds of in-smem pairwise merges: A->B, B->A, A->B
    {
        int p = tid >> 6, lt = tid & 63;
        smem_merge(bufA, bufB,
                   s_off[2*p],   s_off[2*p+1]-s_off[2*p],
                   s_off[2*p+1], s_off[2*p+2]-s_off[2*p+1],
                   s_off[2*p], lt, 64);
    }
    __syncthreads();
    {
        int p = tid >> 7, lt = tid & 127;
        smem_merge(bufB, bufA,
                   s_off[4*p],   s_off[4*p+2]-s_off[4*p],
                   s_off[4*p+2], s_off[4*p+4]-s_off[4*p+2],
                   s_off[4*p], lt, 128);
    }
    __syncthreads();
    smem_merge(bufA, bufB,
               0,        s_off[4],
               s_off[4], s_off[8]-s_off[4],
               0, tid, TPB);
    __syncthreads();

    int nv = s_nv, nwarm = s_nw;
    int kloc = tid * WPT2;

    // phase 2a: keys -> regs; write nt/am (bufA region only)
    ull out[WPT2];
    #pragma unroll
    for (int q = 0; q < WPT2; q++){
        int slot = kloc + q;
        if (slot < nv){
            ull kk = bufB[slot];
            out[q] = kk;
            s_nt[slot] = unfkey((unsigned)(kk >> 32));
            s_am[slot] = sam[(int)(kk & 7u)];
        } else {
            out[q] = 0ULL;
            s_nt[slot] = 1e30f;
            s_am[slot] = 0.f;
        }
    }
    __syncthreads();
    // phase 2b: gathers; write y/dd (clobbers bufB — keys already in regs)
    #pragma unroll
    for (int q = 0; q < WPT2; q++){
        int slot = kloc + q;
        if (slot < nv){
            int idx = (int)((out[q] >> 3) & 0x3FFFFFu);
            s_y [slot] = __ldg(&y[idx]);
            s_dd[slot] = __ldg(&dg[idx]);
        } else {
            s_y [slot] = 0.f;
            s_dd[slot] = 1.f;
        }
    }
    __syncthreads();

    float tprev0 = kloc ? s_nt[kloc-1] : s_nt[0];
    float a = g_ka, c = g_kc;

    // ---- pass B: per-thread Mobius segment (fp32) ----
    float m0f=1.f, m1f=0.f, m2f=0.f, m3f=1.f;
    {
        float tprev = tprev0;
        #pragma unroll
        for (int q = 0; q < WPT2; q++){
            int slot = kloc + q;
            float nt = s_nt[slot];
            float dd = s_dd[slot];
            float amp = s_am[slot];
            float dt = nt - tprev; tprev = nt;
            float phi2 = expf(-2.f*c*dt);
            float V = amp, U = a*amp;
            float Am = dd + U*V;
            float e00 = (Am - 2.f*U*V)*phi2, e01 = V*V, e10 = -U*U*phi2, e11 = Am;
            float r0 = e00*m0f + e01*m2f, r1 = e00*m1f + e01*m3f;
            float r2 = e10*m0f + e11*m2f, r3 = e10*m1f + e11*m3f;
            float mx = fmaxf(fmaxf(fabsf(r0),fabsf(r1)), fmaxf(fabsf(r2),fabsf(r3)));
            float sc = (mx > 0.f) ? 1.f/mx : 1.f;
            m0f=r0*sc; m1f=r1*sc; m2f=r2*sc; m3f=r3*sc;
        }
    }
    // ---- fp64 warp scan of matrices ----
    double W[4] = {(double)m0f,(double)m1f,(double)m2f,(double)m3f};
    #pragma unroll
    for (int d = 1; d < 32; d <<= 1){
        double Q[4];
        #pragma unroll
        for (int q = 0; q < 4; q++) Q[q] = __shfl_up_sync(FULL, W[q], d);
        if (lane >= d){ double R[4]; mmulD(R, W, Q); W[0]=R[0]; W[1]=R[1]; W[2]=R[2]; W[3]=R[3]; }
    }
    if (lane == 31){ sWin[wid][0]=W[0]; sWin[wid][1]=W[1]; sWin[wid][2]=W[2]; sWin[wid][3]=W[3]; }
    __syncthreads();
    if (tid == 0){
        double run[4] = {sWin[0][0], sWin[0][1], sWin[0][2], sWin[0][3]};
        for (int w = 1; w < NWARP; w++){
            double cu[4] = {sWin[w][0], sWin[w][1], sWin[w][2], sWin[w][3]};
            double r[4]; mmulD(r, cu, run);
            for (int q=0;q<4;q++){ run[q]=r[q]; sWin[w][q]=r[q]; }
        }
    }
    __syncthreads();
    float Sp0;
    {
        double Pd[4];
        #pragma unroll
        for (int q = 0; q < 4; q++) Pd[q] = __shfl_up_sync(FULL, W[q], 1);
        if (lane == 0){ Pd[0]=1.0; Pd[1]=0.0; Pd[2]=0.0; Pd[3]=1.0; }
        double Wd[4];
        if (wid == 0){ Wd[0]=1.0; Wd[1]=0.0; Wd[2]=0.0; Wd[3]=1.0; }
        else { for (int q=0;q<4;q++) Wd[q] = sWin[wid-1][q]; }
        double Ex[4]; mmulD(Ex, Pd, Wd);
        Sp0 = (float)(Ex[1] / Ex[3]);   // window starts at S = 0
    }

    // ---- pass C: f-affine + quadratic likelihood accumulation (owned slots) ----
    double Sa, Sb;
    double qaa = 0.0, qab = 0.0, qbb = 0.0, slog = 0.0;
    {
        float Sp = Sp0;
        float al = 1.f, be = 0.f;
        float tprev = tprev0;
        #pragma unroll
        for (int q = 0; q < WPT2; q++){
            int slot = kloc + q;
            float nt = s_nt[slot];
            float dd = s_dd[slot];
            float amp = s_am[slot];
            float dt = nt - tprev; tprev = nt;
            float phi = expf(-c*dt);
            float phi2 = phi*phi;
            float V = amp, U = a*V;
            float Am = dd + U*V;
            float S = phi2 * Sp;
            float D = Am - U*U*S;
            float Wc = (V - U*S) / D;
            // z = A*f_t + B with thread-entering f_t
            float Uphi = U * phi;
            float Az = -Uphi * al;
            float Bz = s_y[slot] - Uphi * be;
            if (slot >= nwarm){
                float invD = 1.f / D;
                qaa += (double)(Az*Az*invD);
                qab += (double)(Az*Bz*invD);
                qbb += (double)(Bz*Bz*invD);
                slog += (double)logf(D);
            }
            float an = phi * (1.f - Wc*U);
            float bn = Wc * s_y[slot];
            be = an*be + bn;
            al *= an;
            Sp = S + D*Wc*Wc;
        }
        Sa = (double)al; Sb = (double)be;
    }
    #pragma unroll
    for (int d = 1; d < 32; d <<= 1){
        double Qa = __shfl_up_sync(FULL, Sa, d);
        double Qb = __shfl_up_sync(FULL, Sb, d);
        if (lane >= d){ Sb = Sa*Qb + Sb; Sa = Sa*Qa; }
    }
    if (lane == 31){ sAf[wid][0] = Sa; sAf[wid][1] = Sb; }
    __syncthreads();
    if (tid == 0){
        double ra = sAf[0][0], rb = sAf[0][1];
        for (int w = 1; w < NWARP; w++){
            double ca = sAf[w][0], cb = sAf[w][1];
            rb = ca*rb + cb; ra = ca*ra;
            sAf[w][0] = ra; sAf[w][1] = rb;
        }
    }
    __syncthreads();
    double ft;
    {
        double Ea = __shfl_up_sync(FULL, Sa, 1);
        double Eb = __shfl_up_sync(FULL, Sb, 1);
        if (lane == 0){ Ea = 1.0; Eb = 0.0; }
        double Wb = 0.0;
        if (wid > 0) Wb = sAf[wid-1][1];
        ft = Ea*Wb + Eb;   // thread-entering f (block f0 = 0)
    }

    // ---- evaluate quadratic form ----
    double loc = qaa*ft*ft + 2.0*qab*ft + qbb + slog;
    sred[tid] = loc;
    __syncthreads();
    for (int off = TPB/2; off > 0; off >>= 1){
        if (tid < off) sred[tid] += sred[tid+off];
        __syncthreads();
    }
    if (tid == 0) g_bsum[blk] = sred[0];
}

__global__ void k_final(float* out){
    __shared__ double red[1024];
    int tid = threadIdx.x;
    double s = g_bsum[tid] + g_bsum[tid + 1024];
    if (tid + 2048 < NT2) s += g_bsum[tid + 2048];
    red[tid] = s;
    __syncthreads();
    for (int off = 512; off > 0; off >>= 1){
        if (tid < off) red[tid] += red[tid+off];
        __syncthreads();
    }
    if (tid == 0) out[0] = (float)(0.5 * (red[0] + (double)NTOT * 1.8378770664093454));
}

// ---------------- launch ----------------
extern "C" void kernel_launch(void* const* d_in, const int* in_sizes, int n_in,
                              void* d_out, int out_size){
    const float* t    = (const float*)d_in[0];
    const int*   band = (const int*)  d_in[1];
    const float* y    = (const float*)d_in[2];
    const float* dg   = (const float*)d_in[3];
    const float* lad  = (const float*)d_in[4];
    const float* lg   = (const float*)d_in[5];
    const float* lkp  = (const float*)d_in[6];
    float* out = (float*)d_out;

    k_init    <<<1, 32>>>(lad, lg, lkp);
    k_count   <<<SC_NBLK, TPB>>>(band);
    k_offsets8<<<NBANDS, TPB>>>();
    k_scatter <<<SC_NBLK, TPB>>>(t, band);
    k_fused8  <<<NT2, TPB>>>(y, dg);
    k_final   <<<1, 1024>>>(out);
}

// round 16
// speedup vs baseline: 1.2084x; 1.2084x over previous
#include <cuda_runtime.h>
#include <stdint.h>
#include <math.h>

#define NTOT    (1<<22)
#define NBANDS  8
#define TPB     256

#define SC_CHUNK 2048
#define SC_NBLK  (NTOT/SC_CHUNK)   /* 2048 */
#define SC_L     (SC_CHUNK/TPB)    /* 8    */

#define R_CAP    540672             /* NTOT/8 + 16384 */

#define NT2      2560               /* value tiles */
#define CAP      2560               /* smem window slots */
#define WPT2     (CAP/TPB)          /* 10 */
#define NWARP    (TPB/32)           /* 8 */

#define VMIN     (-8.0)
#define VMAX     (10008.0)
#define WARMW    (1.25)

typedef unsigned long long ull;

// ---------------- static device scratch ----------------
__device__ ull    g_key[8*R_CAP];
__device__ int    g_bcnt[NBANDS*SC_NBLK];
__device__ int    g_boff[NBANDS*SC_NBLK];
__device__ int    g_cnt[NBANDS];
__device__ double g_bsum[NT2];
__device__ float  g_amps[NBANDS], g_lags[NBANDS], g_ka, g_kc;

__device__ __forceinline__ unsigned fkey(float f){
    unsigned u = __float_as_uint(f);
    return (u & 0x80000000u) ? ~u : (u | 0x80000000u);
}
__device__ __forceinline__ float unfkey(unsigned k){
    unsigned u = (k & 0x80000000u) ? (k & 0x7fffffffu) : ~k;
    return __uint_as_float(u);
}

__device__ __forceinline__ void mmulD(double r[4], const double n[4], const double o[4]){
    double t0 = n[0]*o[0] + n[1]*o[2];
    double t1 = n[0]*o[1] + n[1]*o[3];
    double t2 = n[2]*o[0] + n[3]*o[2];
    double t3 = n[2]*o[1] + n[3]*o[3];
    double mx = fmax(fmax(fabs(t0),fabs(t1)), fmax(fabs(t2),fabs(t3)));
    double s  = (mx > 0.0) ? 1.0/mx : 1.0;
    r[0]=t0*s; r[1]=t1*s; r[2]=t2*s; r[3]=t3*s;
}

// ---------------- params ----------------
__global__ void k_init(const float* __restrict__ lad, const float* __restrict__ lg,
                       const float* __restrict__ lkp){
    if (threadIdx.x == 0){
        g_amps[0] = 1.f; g_lags[0] = 0.f;
        for (int b = 1; b < NBANDS; b++){
            g_amps[b] = expf(lad[b-1]);
            g_lags[b] = lg[b-1];
        }
        g_ka = expf(lkp[0]);
        g_kc = expf(lkp[1]);
    }
}

// ---------------- stage 1: histogram (band-major) ----------------
__global__ void k_count(const int* __restrict__ band){
    __shared__ int sc[NBANDS];
    int tid = threadIdx.x;
    if (tid < NBANDS) sc[tid] = 0;
    __syncthreads();
    int cnt[NBANDS];
    #pragma unroll
    for (int b = 0; b < NBANDS; b++) cnt[b] = 0;
    int base = blockIdx.x * SC_CHUNK;
    for (int k = tid; k < SC_CHUNK; k += TPB) cnt[band[base+k]]++;
    #pragma unroll
    for (int b = 0; b < NBANDS; b++) if (cnt[b]) atomicAdd(&sc[b], cnt[b]);
    __syncthreads();
    if (tid < NBANDS) g_bcnt[tid*SC_NBLK + blockIdx.x] = sc[tid];
}

// ---------------- stage 1b: 8 independent per-band scans ----------------
__global__ void k_offsets8(){
    __shared__ int ssum[TPB];
    int b = blockIdx.x;
    int tid = threadIdx.x;
    int v[SC_NBLK/TPB];
    int run = 0;
    #pragma unroll
    for (int q = 0; q < SC_NBLK/TPB; q++){
        v[q] = run;
        run += g_bcnt[b*SC_NBLK + tid*(SC_NBLK/TPB) + q];
    }
    ssum[tid] = run;
    __syncthreads();
    for (int off = 1; off < TPB; off <<= 1){
        int pv = (tid >= off) ? ssum[tid-off] : 0;
        __syncthreads();
        ssum[tid] += pv;
        __syncthreads();
    }
    int excl = tid ? ssum[tid-1] : 0;
    #pragma unroll
    for (int q = 0; q < SC_NBLK/TPB; q++)
        g_boff[b*SC_NBLK + tid*(SC_NBLK/TPB) + q] = excl + v[q];
    if (tid == TPB-1) g_cnt[b] = excl + run;
}

// ---------------- stage 2: stable partition into band regions ----------------
__global__ void k_scatter(const float* __restrict__ t, const int* __restrict__ band){
    __shared__ float s_t[SC_CHUNK];
    __shared__ int   s_b[SC_CHUNK];
    __shared__ int   s_scan[NBANDS*TPB];
    __shared__ float s_lag[NBANDS];
    int tid = threadIdx.x;
    int base = blockIdx.x * SC_CHUNK;
    if (tid < NBANDS) s_lag[tid] = g_lags[tid];
    for (int k = tid; k < SC_CHUNK; k += TPB){
        s_t[k] = t[base+k]; s_b[k] = band[base+k];
    }
    __syncthreads();
    int cnt[NBANDS];
    #pragma unroll
    for (int b = 0; b < NBANDS; b++) cnt[b] = 0;
    #pragma unroll
    for (int j = 0; j < SC_L; j++) cnt[s_b[tid*SC_L + j]]++;
    #pragma unroll
    for (int b = 0; b < NBANDS; b++) s_scan[b*TPB + tid] = cnt[b];
    __syncthreads();
    for (int off = 1; off < TPB; off <<= 1){
        int v[NBANDS];
        #pragma unroll
        for (int b = 0; b < NBANDS; b++) v[b] = (tid >= off) ? s_scan[b*TPB + tid - off] : 0;
        __syncthreads();
        #pragma unroll
        for (int b = 0; b < NBANDS; b++) s_scan[b*TPB + tid] += v[b];
        __syncthreads();
    }
    int pos[NBANDS];
    #pragma unroll
    for (int b = 0; b < NBANDS; b++)
        pos[b] = b*R_CAP + g_boff[b*SC_NBLK + blockIdx.x] + (tid ? s_scan[b*TPB + tid - 1] : 0);
    #pragma unroll
    for (int j = 0; j < SC_L; j++){
        int li = tid*SC_L + j;
        int b = s_b[li];
        float nt = s_t[li] - s_lag[b];
        ull key = ((ull)fkey(nt) << 32) | ((ull)(unsigned)(base + li) << 3) | (unsigned)b;
        g_key[pos[b]++] = key;
    }
}

// ---------------- smem pairwise merge (strict total order: keys unique) ----------------
__device__ __forceinline__ void smem_merge(const ull* S, ull* D,
                                           int aOff, int aLen, int bOff, int bLen,
                                           int dOff, int lt, int nth){
    int total = aLen + bLen;
    if (total <= 0) return;
    int per = (total + nth - 1) / nth;
    int k0 = lt * per;
    if (k0 >= total) return;
    int k1 = k0 + per; if (k1 > total) k1 = total;
    int lo = k0 - bLen; if (lo < 0) lo = 0;
    int hi = k0 < aLen ? k0 : aLen;
    while (lo < hi){
        int mid = (lo + hi) >> 1;
        if (S[aOff + mid] < S[bOff + k0 - mid - 1]) lo = mid + 1; else hi = mid;
    }
    int i = lo, j = k0 - lo;
    for (int k = k0; k < k1; k++){
        bool ta = (j >= bLen) || (i < aLen && S[aOff + i] < S[bOff + j]);
        D[dOff + k] = ta ? S[aOff + i++] : S[bOff + j++];
    }
}

// ---------------- fused: value-window 8-way merge + warmup scans + quadratic likelihood ----------------
__global__ void __launch_bounds__(TPB)
k_fused8(const float* __restrict__ y, const float* __restrict__ dg){
    __shared__ __align__(16) char raw[CAP*16];
    ull*   bufA = (ull*)raw;
    ull*   bufB = (ull*)(raw + CAP*8);
    float* s_nt = (float*)raw;
    float* s_am = (float*)(raw + CAP*4);
    float* s_y  = (float*)(raw + CAP*8);
    float* s_dd = (float*)(raw + CAP*12);
    __shared__ int s_res[24];
    __shared__ int s_off[9], s_gs[8];
    __shared__ int s_nw, s_nv;
    __shared__ double sWin[NWARP][4];
    __shared__ double sAf[NWARP][2];
    __shared__ double sred[TPB];
    __shared__ float  sam[NBANDS];
    const unsigned FULL = 0xFFFFFFFFu;

    int tid = threadIdx.x;
    int lane = tid & 31;
    int wid  = tid >> 5;
    int blk  = blockIdx.x;

    double TW = (VMAX - VMIN) / (double)NT2;
    float vlo = (float)(VMIN + blk*TW);
    float vhi = (float)(VMIN + (blk+1)*TW);
    float wlo = (float)(VMIN + blk*TW - WARMW);

    if (tid < NBANDS) sam[tid] = g_amps[tid];
    if (tid < 24){
        int bb = tid / 3, w = tid % 3;
        float v = (w == 0) ? wlo : (w == 1 ? vlo : vhi);
        ull K = ((ull)fkey(v)) << 32;
        const ull* L = g_key + bb*R_CAP;
        int lo = 0, hi = g_cnt[bb];
        while (lo < hi){
            int mid = (lo + hi) >> 1;
            if (__ldg(&L[mid]) < K) lo = mid + 1; else hi = mid;
        }
        s_res[tid] = lo;
    }
    __syncthreads();
    if (tid == 0){
        int st[8], ln[8], wb[8];
        int tot = 0;
        #pragma unroll
        for (int q = 0; q < 8; q++){
            st[q] = s_res[q*3+0];
            wb[q] = s_res[q*3+1] - st[q];
            ln[q] = s_res[q*3+2] - st[q];
            tot += ln[q];
        }
        if (tot > CAP){   // defensive: trim warmup from left
            int drop = tot - CAP;
            for (int q = 0; q < 8 && drop > 0; q++){
                int d = wb[q] < drop ? wb[q] : drop;
                st[q] += d; ln[q] -= d; wb[q] -= d; drop -= d;
            }
            tot = 0;
            for (int q = 0; q < 8; q++) tot += ln[q];
        }
        int o = 0, nw = 0;
        #pragma unroll
        for (int q = 0; q < 8; q++){
            s_off[q] = o; s_gs[q] = st[q];
            o += ln[q]; nw += wb[q];
        }
        s_off[8] = o; s_nv = o; s_nw = nw;
    }
    __syncthreads();

    // load band segments (coalesced per band)
    #pragma unroll
    for (int q = 0; q < 8; q++){
        const ull* L = g_key + q*R_CAP + s_gs[q];
        int o  = s_off[q];
        int ln = s_off[q+1] - o;
        for (int k = tid; k < ln; k += TPB) bufA[o+k] = __ldg(&L[k]);
    }
    __syncthreads();

    // 3 rounds of in-smem pairwise merges: A->B, B->A, A->B
    {
        int p = tid >> 6, lt = tid & 63;
        smem_merge(bufA, bufB,
                   s_off[2*p],   s_off[2*p+1]-s_off[2*p],
                   s_off[2*p+1], s_off[2*p+2]-s_off[2*p+1],
                   s_off[2*p], lt, 64);
    }
    __syncthreads();
    {
        int p = tid >> 7, lt = tid & 127;
        smem_merge(bufB, bufA,
                   s_off[4*p],   s_off[4*p+2]-s_off[4*p],
                   s_off[4*p+2], s_off[4*p+4]-s_off[4*p+2],
                   s_off[4*p], lt, 128);
    }
    __syncthreads();
    smem_merge(bufA, bufB,
               0,        s_off[4],
               s_off[4], s_off[8]-s_off[4],
               0, tid, TPB);
    __syncthreads();

    int nv = s_nv, nwarm = s_nw;
    int kloc = tid * WPT2;

    // phase 2a: keys -> regs; write nt/am (bufA region only)
    ull out[WPT2];
    #pragma unroll
    for (int q = 0; q < WPT2; q++){
        int slot = kloc + q;
        if (slot < nv){
            ull kk = bufB[slot];
            out[q] = kk;
            s_nt[slot] = unfkey((unsigned)(kk >> 32));
            s_am[slot] = sam[(int)(kk & 7u)];
        } else {
            out[q] = 0ULL;
            s_nt[slot] = 1e30f;
            s_am[slot] = 0.f;
        }
    }
    __syncthreads();
    // phase 2b: gathers; write y/dd (clobbers bufB — keys already in regs)
    #pragma unroll
    for (int q = 0; q < WPT2; q++){
        int slot = kloc + q;
        if (slot < nv){
            int idx = (int)((out[q] >> 3) & 0x3FFFFFu);
            s_y [slot] = __ldg(&y[idx]);
            s_dd[slot] = __ldg(&dg[idx]);
        } else {
            s_y [slot] = 0.f;
            s_dd[slot] = 1.f;
        }
    }
    __syncthreads();

    float tprev0 = kloc ? s_nt[kloc-1] : s_nt[0];
    float a = g_ka, c = g_kc;

    // ---- pass B: per-thread Mobius segment (fp32) ----
    float m0f=1.f, m1f=0.f, m2f=0.f, m3f=1.f;
    {
        float tprev = tprev0;
        #pragma unroll
        for (int q = 0; q < WPT2; q++){
            int slot = kloc + q;
            float nt = s_nt[slot];
            float dd = s_dd[slot];
            float amp = s_am[slot];
            float dt = nt - tprev; tprev = nt;
            float phi2 = expf(-2.f*c*dt);
            float V = amp, U = a*amp;
            float Am = dd + U*V;
            float e00 = (Am - 2.f*U*V)*phi2, e01 = V*V, e10 = -U*U*phi2, e11 = Am;
            float r0 = e00*m0f + e01*m2f, r1 = e00*m1f + e01*m3f;
            float r2 = e10*m0f + e11*m2f, r3 = e10*m1f + e11*m3f;
            float mx = fmaxf(fmaxf(fabsf(r0),fabsf(r1)), fmaxf(fabsf(r2),fabsf(r3)));
            float sc = (mx > 0.f) ? 1.f/mx : 1.f;
            m0f=r0*sc; m1f=r1*sc; m2f=r2*sc; m3f=r3*sc;
        }
    }
    // ---- fp64 warp scan of matrices ----
    double W[4] = {(double)m0f,(double)m1f,(double)m2f,(double)m3f};
    #pragma unroll
    for (int d = 1; d < 32; d <<= 1){
        double Q[4];
        #pragma unroll
        for (int q = 0; q < 4; q++) Q[q] = __shfl_up_sync(FULL, W[q], d);
        if (lane >= d){ double R[4]; mmulD(R, W, Q); W[0]=R[0]; W[1]=R[1]; W[2]=R[2]; W[3]=R[3]; }
    }
    if (lane == 31){ sWin[wid][0]=W[0]; sWin[wid][1]=W[1]; sWin[wid][2]=W[2]; sWin[wid][3]=W[3]; }
    __syncthreads();
    if (tid == 0){
        double run[4] = {sWin[0][0], sWin[0][1], sWin[0][2], sWin[0][3]};
        for (int w = 1; w < NWARP; w++){
            double cu[4] = {sWin[w][0], sWin[w][1], sWin[w][2], sWin[w][3]};
            double r[4]; mmulD(r, cu, run);
            for (int q=0;q<4;q++){ run[q]=r[q]; sWin[w][q]=r[q]; }
        }
    }
    __syncthreads();
    float Sp0;
    {
        double Pd[4];
        #pragma unroll
        for (int q = 0; q < 4; q++) Pd[q] = __shfl_up_sync(FULL, W[q], 1);
        if (lane == 0){ Pd[0]=1.0; Pd[1]=0.0; Pd[2]=0.0; Pd[3]=1.0; }
        double Wd[4];
        if (wid == 0){ Wd[0]=1.0; Wd[1]=0.0; Wd[2]=0.0; Wd[3]=1.0; }
        else { for (int q=0;q<4;q++) Wd[q] = sWin[wid-1][q]; }
        double Ex[4]; mmulD(Ex, Pd, Wd);
        Sp0 = (float)(Ex[1] / Ex[3]);   // window starts at S = 0
    }

    // ---- pass C: f-affine + fp32 quadratic likelihood accumulation (owned slots) ----
    double Sa, Sb;
    float qaa = 0.f, qab = 0.f, qbb = 0.f, slog = 0.f;
    {
        float Sp = Sp0;
        float al = 1.f, be = 0.f;
        float tprev = tprev0;
        #pragma unroll
        for (int q = 0; q < WPT2; q++){
            int slot = kloc + q;
            float nt = s_nt[slot];
            float dd = s_dd[slot];
            float amp = s_am[slot];
            float dt = nt - tprev; tprev = nt;
            float phi = expf(-c*dt);
            float phi2 = phi*phi;
            float V = amp, U = a*V;
            float Am = dd + U*V;
            float S = phi2 * Sp;
            float D = Am - U*U*S;
            float Wc = (V - U*S) / D;
            // z = Az*f_t + Bz with thread-entering f_t
            float Uphi = U * phi;
            float Az = -Uphi * al;
            float Bz = s_y[slot] - Uphi * be;
            if (slot >= nwarm){
                float invD = 1.f / D;
                qaa = fmaf(Az*Az, invD, qaa);
                qab = fmaf(Az*Bz, invD, qab);
                qbb = fmaf(Bz*Bz, invD, qbb);
                slog += __logf(D);
            }
            float an = phi * (1.f - Wc*U);
            float bn = Wc * s_y[slot];
            be = an*be + bn;
            al *= an;
            Sp = S + D*Wc*Wc;
        }
        Sa = (double)al; Sb = (double)be;
    }
    #pragma unroll
    for (int d = 1; d < 32; d <<= 1){
        double Qa = __shfl_up_sync(FULL, Sa, d);
        double Qb = __shfl_up_sync(FULL, Sb, d);
        if (lane >= d){ Sb = Sa*Qb + Sb; Sa = Sa*Qa; }
    }
    if (lane == 31){ sAf[wid][0] = Sa; sAf[wid][1] = Sb; }
    __syncthreads();
    if (tid == 0){
        double ra = sAf[0][0], rb = sAf[0][1];
        for (int w = 1; w < NWARP; w++){
            double ca = sAf[w][0], cb = sAf[w][1];
            rb = ca*rb + cb; ra = ca*ra;
            sAf[w][0] = ra; sAf[w][1] = rb;
        }
    }
    __syncthreads();
    double ft;
    {
        double Ea = __shfl_up_sync(FULL, Sa, 1);
        double Eb = __shfl_up_sync(FULL, Sb, 1);
        if (lane == 0){ Ea = 1.0; Eb = 0.0; }
        double Wb = 0.0;
        if (wid > 0) Wb = sAf[wid-1][1];
        ft = Ea*Wb + Eb;   // thread-entering f (block f0 = 0)
    }

    // ---- evaluate quadratic form (fp64, one per thread) ----
    double loc = (double)qaa*ft*ft + 2.0*(double)qab*ft + (double)qbb + (double)slog;
    sred[tid] = loc;
    __syncthreads();
    for (int off = TPB/2; off > 0; off >>= 1){
        if (tid < off) sred[tid] += sred[tid+off];
        __syncthreads();
    }
    if (tid == 0) g_bsum[blk] = sred[0];
}

__global__ void k_final(float* out){
    __shared__ double red[1024];
    int tid = threadIdx.x;
    double s = g_bsum[tid] + g_bsum[tid + 1024];
    if (tid + 2048 < NT2) s += g_bsum[tid + 2048];
    red[tid] = s;
    __syncthreads();
    for (int off = 512; off > 0; off >>= 1){
        if (tid < off) red[tid] += red[tid+off];
        __syncthreads();
    }
    if (tid == 0) out[0] = (float)(0.5 * (red[0] + (double)NTOT * 1.8378770664093454));
}

// ---------------- launch ----------------
extern "C" void kernel_launch(void* const* d_in, const int* in_sizes, int n_in,
                              void* d_out, int out_size){
    const float* t    = (const float*)d_in[0];
    const int*   band = (const int*)  d_in[1];
    const float* y    = (const float*)d_in[2];
    const float* dg   = (const float*)d_in[3];
    const float* lad  = (const float*)d_in[4];
    const float* lg   = (const float*)d_in[5];
    const float* lkp  = (const float*)d_in[6];
    float* out = (float*)d_out;

    k_init    <<<1, 32>>>(lad, lg, lkp);
    k_count   <<<SC_NBLK, TPB>>>(band);
    k_offsets8<<<NBANDS, TPB>>>();
    k_scatter <<<SC_NBLK, TPB>>>(t, band);
    k_fused8  <<<NT2, TPB>>>(y, dg);
    k_final   <<<1, 1024>>>(out);
}

// round 17
// speedup vs baseline: 1.2452x; 1.0304x over previous
#include <cuda_runtime.h>
#include <stdint.h>
#include <math.h>

#define NTOT    (1<<22)
#define NBANDS  8
#define TPB     256

#define SC_CHUNK 2048
#define SC_NBLK  (NTOT/SC_CHUNK)   /* 2048 */
#define SC_L     (SC_CHUNK/TPB)    /* 8    */

#define R_CAP    540672             /* NTOT/8 + 16384 */

#define NT2      2560               /* value tiles */
#define CAP      2304               /* smem window slots (9*256) */
#define WPT2     (CAP/TPB)          /* 9 */
#define NWARP    (TPB/32)           /* 8 */

#define VMIN     (-8.0)
#define VMAX     (10008.0)
#define WARMW    (0.55)

typedef unsigned long long ull;

// ---------------- static device scratch ----------------
__device__ ull    g_key[8*R_CAP];
__device__ int    g_bcnt[NBANDS*SC_NBLK];
__device__ int    g_boff[NBANDS*SC_NBLK];
__device__ int    g_cnt[NBANDS];
__device__ double g_bsum[NT2];
__device__ float  g_amps[NBANDS], g_lags[NBANDS], g_ka, g_kc;

__device__ __forceinline__ unsigned fkey(float f){
    unsigned u = __float_as_uint(f);
    return (u & 0x80000000u) ? ~u : (u | 0x80000000u);
}
__device__ __forceinline__ float unfkey(unsigned k){
    unsigned u = (k & 0x80000000u) ? (k & 0x7fffffffu) : ~k;
    return __uint_as_float(u);
}

__device__ __forceinline__ void mmulD(double r[4], const double n[4], const double o[4]){
    double t0 = n[0]*o[0] + n[1]*o[2];
    double t1 = n[0]*o[1] + n[1]*o[3];
    double t2 = n[2]*o[0] + n[3]*o[2];
    double t3 = n[2]*o[1] + n[3]*o[3];
    double mx = fmax(fmax(fabs(t0),fabs(t1)), fmax(fabs(t2),fabs(t3)));
    double s  = (mx > 0.0) ? 1.0/mx : 1.0;
    r[0]=t0*s; r[1]=t1*s; r[2]=t2*s; r[3]=t3*s;
}

// ---------------- params ----------------
__global__ void k_init(const float* __restrict__ lad, const float* __restrict__ lg,
                       const float* __restrict__ lkp){
    if (threadIdx.x == 0){
        g_amps[0] = 1.f; g_lags[0] = 0.f;
        for (int b = 1; b < NBANDS; b++){
            g_amps[b] = expf(lad[b-1]);
            g_lags[b] = lg[b-1];
        }
        g_ka = expf(lkp[0]);
        g_kc = expf(lkp[1]);
    }
}

// ---------------- stage 1: histogram (band-major) ----------------
__global__ void k_count(const int* __restrict__ band){
    __shared__ int sc[NBANDS];
    int tid = threadIdx.x;
    if (tid < NBANDS) sc[tid] = 0;
    __syncthreads();
    int cnt[NBANDS];
    #pragma unroll
    for (int b = 0; b < NBANDS; b++) cnt[b] = 0;
    int base = blockIdx.x * SC_CHUNK;
    for (int k = tid; k < SC_CHUNK; k += TPB) cnt[band[base+k]]++;
    #pragma unroll
    for (int b = 0; b < NBANDS; b++) if (cnt[b]) atomicAdd(&sc[b], cnt[b]);
    __syncthreads();
    if (tid < NBANDS) g_bcnt[tid*SC_NBLK + blockIdx.x] = sc[tid];
}

// ---------------- stage 1b: 8 independent per-band scans ----------------
__global__ void k_offsets8(){
    __shared__ int ssum[TPB];
    int b = blockIdx.x;
    int tid = threadIdx.x;
    int v[SC_NBLK/TPB];
    int run = 0;
    #pragma unroll
    for (int q = 0; q < SC_NBLK/TPB; q++){
        v[q] = run;
        run += g_bcnt[b*SC_NBLK + tid*(SC_NBLK/TPB) + q];
    }
    ssum[tid] = run;
    __syncthreads();
    for (int off = 1; off < TPB; off <<= 1){
        int pv = (tid >= off) ? ssum[tid-off] : 0;
        __syncthreads();
        ssum[tid] += pv;
        __syncthreads();
    }
    int excl = tid ? ssum[tid-1] : 0;
    #pragma unroll
    for (int q = 0; q < SC_NBLK/TPB; q++)
        g_boff[b*SC_NBLK + tid*(SC_NBLK/TPB) + q] = excl + v[q];
    if (tid == TPB-1) g_cnt[b] = excl + run;
}

// ---------------- stage 2: stable partition into band regions ----------------
__global__ void k_scatter(const float* __restrict__ t, const int* __restrict__ band){
    __shared__ float s_t[SC_CHUNK];
    __shared__ int   s_b[SC_CHUNK];
    __shared__ int   s_scan[NBANDS*TPB];
    __shared__ float s_lag[NBANDS];
    int tid = threadIdx.x;
    int base = blockIdx.x * SC_CHUNK;
    if (tid < NBANDS) s_lag[tid] = g_lags[tid];
    for (int k = tid; k < SC_CHUNK; k += TPB){
        s_t[k] = t[base+k]; s_b[k] = band[base+k];
    }
    __syncthreads();
    int cnt[NBANDS];
    #pragma unroll
    for (int b = 0; b < NBANDS; b++) cnt[b] = 0;
    #pragma unroll
    for (int j = 0; j < SC_L; j++) cnt[s_b[tid*SC_L + j]]++;
    #pragma unroll
    for (int b = 0; b < NBANDS; b++) s_scan[b*TPB + tid] = cnt[b];
    __syncthreads();
    for (int off = 1; off < TPB; off <<= 1){
        int v[NBANDS];
        #pragma unroll
        for (int b = 0; b < NBANDS; b++) v[b] = (tid >= off) ? s_scan[b*TPB + tid - off] : 0;
        __syncthreads();
        #pragma unroll
        for (int b = 0; b < NBANDS; b++) s_scan[b*TPB + tid] += v[b];
        __syncthreads();
    }
    int pos[NBANDS];
    #pragma unroll
    for (int b = 0; b < NBANDS; b++)
        pos[b] = b*R_CAP + g_boff[b*SC_NBLK + blockIdx.x] + (tid ? s_scan[b*TPB + tid - 1] : 0);
    #pragma unroll
    for (int j = 0; j < SC_L; j++){
        int li = tid*SC_L + j;
        int b = s_b[li];
        float nt = s_t[li] - s_lag[b];
        ull key = ((ull)fkey(nt) << 32) | ((ull)(unsigned)(base + li) << 3) | (unsigned)b;
        g_key[pos[b]++] = key;
    }
}

// ---------------- smem pairwise merge (strict total order: keys unique) ----------------
__device__ __forceinline__ void smem_merge(const ull* S, ull* D,
                                           int aOff, int aLen, int bOff, int bLen,
                                           int dOff, int lt, int nth){
    int total = aLen + bLen;
    if (total <= 0) return;
    int per = (total + nth - 1) / nth;
    int k0 = lt * per;
    if (k0 >= total) return;
    int k1 = k0 + per; if (k1 > total) k1 = total;
    int lo = k0 - bLen; if (lo < 0) lo = 0;
    int hi = k0 < aLen ? k0 : aLen;
    while (lo < hi){
        int mid = (lo + hi) >> 1;
        if (S[aOff + mid] < S[bOff + k0 - mid - 1]) lo = mid + 1; else hi = mid;
    }
    int i = lo, j = k0 - lo;
    for (int k = k0; k < k1; k++){
        bool ta = (j >= bLen) || (i < aLen && S[aOff + i] < S[bOff + j]);
        D[dOff + k] = ta ? S[aOff + i++] : S[bOff + j++];
    }
}

// ---------------- fused: value-window 8-way merge + warmup scans + quadratic likelihood ----------------
__global__ void __launch_bounds__(TPB)
k_fused8(const float* __restrict__ y, const float* __restrict__ dg){
    __shared__ __align__(16) char raw[CAP*16];
    ull*   bufA = (ull*)raw;
    ull*   bufB = (ull*)(raw + CAP*8);
    float* s_nt = (float*)raw;
    float* s_am = (float*)(raw + CAP*4);
    float* s_y  = (float*)(raw + CAP*8);
    float* s_dd = (float*)(raw + CAP*12);
    __shared__ int s_res[24];
    __shared__ int s_off[9], s_gs[8];
    __shared__ int s_nw, s_nv;
    __shared__ double sWin[NWARP][4];
    __shared__ double sAf[NWARP][2];
    __shared__ double sred[TPB];
    __shared__ float  sam[NBANDS];
    const unsigned FULL = 0xFFFFFFFFu;

    int tid = threadIdx.x;
    int lane = tid & 31;
    int wid  = tid >> 5;
    int blk  = blockIdx.x;

    double TW = (VMAX - VMIN) / (double)NT2;
    float vlo = (float)(VMIN + blk*TW);
    float vhi = (float)(VMIN + (blk+1)*TW);
    float wlo = (float)(VMIN + blk*TW - WARMW);

    if (tid < NBANDS) sam[tid] = g_amps[tid];
    if (tid < 24){
        int bb = tid / 3, w = tid % 3;
        float v = (w == 0) ? wlo : (w == 1 ? vlo : vhi);
        ull K = ((ull)fkey(v)) << 32;
        const ull* L = g_key + bb*R_CAP;
        int lo = 0, hi = g_cnt[bb];
        while (lo < hi){
            int mid = (lo + hi) >> 1;
            if (__ldg(&L[mid]) < K) lo = mid + 1; else hi = mid;
        }
        s_res[tid] = lo;
    }
    __syncthreads();
    if (tid == 0){
        int st[8], ln[8], wb[8];
        int tot = 0;
        #pragma unroll
        for (int q = 0; q < 8; q++){
            st[q] = s_res[q*3+0];
            wb[q] = s_res[q*3+1] - st[q];
            ln[q] = s_res[q*3+2] - st[q];
            tot += ln[q];
        }
        if (tot > CAP){   // defensive: trim warmup from left
            int drop = tot - CAP;
            for (int q = 0; q < 8 && drop > 0; q++){
                int d = wb[q] < drop ? wb[q] : drop;
                st[q] += d; ln[q] -= d; wb[q] -= d; drop -= d;
            }
            tot = 0;
            for (int q = 0; q < 8; q++) tot += ln[q];
        }
        int o = 0, nw = 0;
        #pragma unroll
        for (int q = 0; q < 8; q++){
            s_off[q] = o; s_gs[q] = st[q];
            o += ln[q]; nw += wb[q];
        }
        s_off[8] = o; s_nv = o; s_nw = nw;
    }
    __syncthreads();

    // load band segments (coalesced per band)
    #pragma unroll
    for (int q = 0; q < 8; q++){
        const ull* L = g_key + q*R_CAP + s_gs[q];
        int o  = s_off[q];
        int ln = s_off[q+1] - o;
        for (int k = tid; k < ln; k += TPB) bufA[o+k] = __ldg(&L[k]);
    }
    __syncthreads();

    // 3 rounds of in-smem pairwise merges: A->B, B->A, A->B
    {
        int p = tid >> 6, lt = tid & 63;
        smem_merge(bufA, bufB,
                   s_off[2*p],   s_off[2*p+1]-s_off[2*p],
                   s_off[2*p+1], s_off[2*p+2]-s_off[2*p+1],
                   s_off[2*p], lt, 64);
    }
    __syncthreads();
    {
        int p = tid >> 7, lt = tid & 127;
        smem_merge(bufB, bufA,
                   s_off[4*p],   s_off[4*p+2]-s_off[4*p],
                   s_off[4*p+2], s_off[4*p+4]-s_off[4*p+2],
                   s_off[4*p], lt, 128);
    }
    __syncthreads();
    smem_merge(bufA, bufB,
               0,        s_off[4],
               s_off[4], s_off[8]-s_off[4],
               0, tid, TPB);
    __syncthreads();

    int nv = s_nv, nwarm = s_nw;
    int kloc = tid * WPT2;

    // phase 2a: keys -> regs; write nt/am (bufA region only)
    ull out[WPT2];
    #pragma unroll
    for (int q = 0; q < WPT2; q++){
        int slot = kloc + q;
        if (slot < nv){
            ull kk = bufB[slot];
            out[q] = kk;
            s_nt[slot] = unfkey((unsigned)(kk >> 32));
            s_am[slot] = sam[(int)(kk & 7u)];
        } else {
            out[q] = 0ULL;
            s_nt[slot] = 1e30f;
            s_am[slot] = 0.f;
        }
    }
    __syncthreads();
    // phase 2b: gathers; write y/dd (clobbers bufB — keys already in regs)
    #pragma unroll
    for (int q = 0; q < WPT2; q++){
        int slot = kloc + q;
        if (slot < nv){
            int idx = (int)((out[q] >> 3) & 0x3FFFFFu);
            s_y [slot] = __ldg(&y[idx]);
            s_dd[slot] = __ldg(&dg[idx]);
        } else {
            s_y [slot] = 0.f;
            s_dd[slot] = 1.f;
        }
    }
    __syncthreads();

    float tprev0 = kloc ? s_nt[kloc-1] : s_nt[0];
    float a = g_ka, c = g_kc;

    // ---- pass B: per-thread Mobius segment (fp32) + phi register cache ----
    float phis[WPT2];
    float m0f=1.f, m1f=0.f, m2f=0.f, m3f=1.f;
    {
        float tprev = tprev0;
        #pragma unroll
        for (int q = 0; q < WPT2; q++){
            int slot = kloc + q;
            float nt = s_nt[slot];
            float dd = s_dd[slot];
            float amp = s_am[slot];
            float dt = nt - tprev; tprev = nt;
            float phi = __expf(-c*dt);
            phis[q] = phi;
            float phi2 = phi*phi;
            float V = amp, U = a*amp;
            float Am = dd + U*V;
            float e00 = (Am - 2.f*U*V)*phi2, e01 = V*V, e10 = -U*U*phi2, e11 = Am;
            float r0 = e00*m0f + e01*m2f, r1 = e00*m1f + e01*m3f;
            float r2 = e10*m0f + e11*m2f, r3 = e10*m1f + e11*m3f;
            float mx = fmaxf(fmaxf(fabsf(r0),fabsf(r1)), fmaxf(fabsf(r2),fabsf(r3)));
            float sc = (mx > 0.f) ? __fdividef(1.f, mx) : 1.f;
            m0f=r0*sc; m1f=r1*sc; m2f=r2*sc; m3f=r3*sc;
        }
    }
    // ---- fp64 warp scan of matrices ----
    double W[4] = {(double)m0f,(double)m1f,(double)m2f,(double)m3f};
    #pragma unroll
    for (int d = 1; d < 32; d <<= 1){
        double Q[4];
        #pragma unroll
        for (int q = 0; q < 4; q++) Q[q] = __shfl_up_sync(FULL, W[q], d);
        if (lane >= d){ double R[4]; mmulD(R, W, Q); W[0]=R[0]; W[1]=R[1]; W[2]=R[2]; W[3]=R[3]; }
    }
    if (lane == 31){ sWin[wid][0]=W[0]; sWin[wid][1]=W[1]; sWin[wid][2]=W[2]; sWin[wid][3]=W[3]; }
    __syncthreads();
    if (tid == 0){
        double run[4] = {sWin[0][0], sWin[0][1], sWin[0][2], sWin[0][3]};
        for (int w = 1; w < NWARP; w++){
            double cu[4] = {sWin[w][0], sWin[w][1], sWin[w][2], sWin[w][3]};
            double r[4]; mmulD(r, cu, run);
            for (int q=0;q<4;q++){ run[q]=r[q]; sWin[w][q]=r[q]; }
        }
    }
    __syncthreads();
    float Sp0;
    {
        double Pd[4];
        #pragma unroll
        for (int q = 0; q < 4; q++) Pd[q] = __shfl_up_sync(FULL, W[q], 1);
        if (lane == 0){ Pd[0]=1.0; Pd[1]=0.0; Pd[2]=0.0; Pd[3]=1.0; }
        double Wd[4];
        if (wid == 0){ Wd[0]=1.0; Wd[1]=0.0; Wd[2]=0.0; Wd[3]=1.0; }
        else { for (int q=0;q<4;q++) Wd[q] = sWin[wid-1][q]; }
        double Ex[4]; mmulD(Ex, Pd, Wd);
        Sp0 = (float)(Ex[1] / Ex[3]);   // window starts at S = 0
    }

    // ---- pass C: f-affine + fp32 quadratic likelihood accumulation (owned slots) ----
    double Sa, Sb;
    float qaa = 0.f, qab = 0.f, qbb = 0.f, slog = 0.f;
    {
        float Sp = Sp0;
        float al = 1.f, be = 0.f;
        #pragma unroll
        for (int q = 0; q < WPT2; q++){
            int slot = kloc + q;
            float dd = s_dd[slot];
            float amp = s_am[slot];
            float phi = phis[q];
            float phi2 = phi*phi;
            float V = amp, U = a*V;
            float Am = dd + U*V;
            float S = phi2 * Sp;
            float D = Am - U*U*S;
            float Wc = __fdividef(V - U*S, D);
            // z = Az*f_t + Bz with thread-entering f_t
            float Uphi = U * phi;
            float Az = -Uphi * al;
            float Bz = s_y[slot] - Uphi * be;
            if (slot >= nwarm){
                float invD = __fdividef(1.f, D);
                qaa = fmaf(Az*Az, invD, qaa);
                qab = fmaf(Az*Bz, invD, qab);
                qbb = fmaf(Bz*Bz, invD, qbb);
                slog += __logf(D);
            }
            float an = phi * (1.f - Wc*U);
            float bn = Wc * s_y[slot];
            be = an*be + bn;
            al *= an;
            Sp = S + D*Wc*Wc;
        }
        Sa = (double)al; Sb = (double)be;
    }
    #pragma unroll
    for (int d = 1; d < 32; d <<= 1){
        double Qa = __shfl_up_sync(FULL, Sa, d);
        double Qb = __shfl_up_sync(FULL, Sb, d);
        if (lane >= d){ Sb = Sa*Qb + Sb; Sa = Sa*Qa; }
    }
    if (lane == 31){ sAf[wid][0] = Sa; sAf[wid][1] = Sb; }
    __syncthreads();
    if (tid == 0){
        double ra = sAf[0][0], rb = sAf[0][1];
        for (int w = 1; w < NWARP; w++){
            double ca = sAf[w][0], cb = sAf[w][1];
            rb = ca*rb + cb; ra = ca*ra;
            sAf[w][0] = ra; sAf[w][1] = rb;
        }
    }
    __syncthreads();
    double ft;
    {
        double Ea = __shfl_up_sync(FULL, Sa, 1);
        double Eb = __shfl_up_sync(FULL, Sb, 1);
        if (lane == 0){ Ea = 1.0; Eb = 0.0; }
        double Wb = 0.0;
        if (wid > 0) Wb = sAf[wid-1][1];
        ft = Ea*Wb + Eb;   // thread-entering f (block f0 = 0)
    }

    // ---- evaluate quadratic form (fp64, one per thread) ----
    double loc = (double)qaa*ft*ft + 2.0*(double)qab*ft + (double)qbb + (double)slog;
    sred[tid] = loc;
    __syncthreads();
    for (int off = TPB/2; off > 0; off >>= 1){
        if (tid < off) sred[tid] += sred[tid+off];
        __syncthreads();
    }
    if (tid == 0) g_bsum[blk] = sred[0];
}

__global__ void k_final(float* out){
    __shared__ double red[1024];
    int tid = threadIdx.x;
    double s = g_bsum[tid] + g_bsum[tid + 1024];
    if (tid + 2048 < NT2) s += g_bsum[tid + 2048];
    red[tid] = s;
    __syncthreads();
    for (int off = 512; off > 0; off >>= 1){
        if (tid < off) red[tid] += red[tid+off];
        __syncthreads();
    }
    if (tid == 0) out[0] = (float)(0.5 * (red[0] + (double)NTOT * 1.8378770664093454));
}

// ---------------- launch ----------------
extern "C" void kernel_launch(void* const* d_in, const int* in_sizes, int n_in,
                              void* d_out, int out_size){
    const float* t    = (const float*)d_in[0];
    const int*   band = (const int*)  d_in[1];
    const float* y    = (const float*)d_in[2];
    const float* dg   = (const float*)d_in[3];
    const float* lad  = (const float*)d_in[4];
    const float* lg   = (const float*)d_in[5];
    const float* lkp  = (const float*)d_in[6];
    float* out = (float*)d_out;

    k_init    <<<1, 32>>>(lad, lg, lkp);
    k_count   <<<SC_NBLK, TPB>>>(band);
    k_offsets8<<<NBANDS, TPB>>>();
    k_scatter <<<SC_NBLK, TPB>>>(t, band);
    k_fused8  <<<NT2, TPB>>>(y, dg);
    k_final   <<<1, 1024>>>(out);
}